// round 15
// baseline (speedup 1.0000x reference)
#include <cuda_runtime.h>
#include <cuda_fp16.h>
#include <cstdint>
#include <cstddef>

#define BATCH 64
#define INF   1024
#define OUTF  1024
#define NEXP  8
#define HID   8
#define SPLITS 16

// c[e][b] = sum_f att[b,f] * align_conv[f,e]
__device__ float g_c[NEXP * BATCH];
// split-K RAW partials [kz][o][b] (4 MB static scratch); c applied in reduce
__device__ float g_part[SPLITS * OUTF * BATCH];
// one completion counter per o-tile; 17 arrivals (16 kz CTAs + gate CTA).
// Self-resetting: the 17th arriver reduces, then stores 0 -> deterministic
// across graph replays (zero-init covers the first run).
__device__ int g_cnt[8];

// ---------------------------------------------------------------------------
// arch-agnostic tensor-core helpers (sm_80+ PTX: valid at target sm_103)
// ---------------------------------------------------------------------------
__device__ __forceinline__ uint32_t smem_u32(const void* p) {
    uint32_t a;
    asm("{ .reg .u64 t; cvta.to.shared.u64 t, %1; cvt.u32.u64 %0, t; }"
        : "=r"(a) : "l"(p));
    return a;
}

__device__ __forceinline__ void ldsm4(uint32_t* r, uint32_t addr) {
    asm volatile("ldmatrix.sync.aligned.m8n8.x4.shared.b16 {%0,%1,%2,%3}, [%4];"
                 : "=r"(r[0]), "=r"(r[1]), "=r"(r[2]), "=r"(r[3]) : "r"(addr));
}

__device__ __forceinline__ void mma16816(float* d, const uint32_t* a,
                                         uint32_t b0, uint32_t b1) {
    asm volatile(
        "mma.sync.aligned.m16n8k16.row.col.f32.f16.f16.f32 "
        "{%0,%1,%2,%3}, {%4,%5,%6,%7}, {%8,%9}, {%0,%1,%2,%3};"
        : "+f"(d[0]), "+f"(d[1]), "+f"(d[2]), "+f"(d[3])
        : "r"(a[0]), "r"(a[1]), "r"(a[2]), "r"(a[3]), "r"(b0), "r"(b1));
}

__device__ __forceinline__ uint32_t h2bits(float a, float b) {
    __half2 h = __floats2half2_rn(a, b);   // low = a, high = b (k-order)
    return *reinterpret_cast<uint32_t*>(&h);
}

__device__ __forceinline__ float tanh_fast(float v) {
    float r;
    asm("tanh.approx.f32 %0, %1;" : "=f"(r) : "f"(v));
    return r;
}

// ---------------------------------------------------------------------------
// Reduce one o-tile (128 o x 64 b): y[b][o] = sum_kz c[b,e(kz)] * part[kz][o][b]
// Whole-CTA (256 threads); fixed summation order -> deterministic.
// ---------------------------------------------------------------------------
__device__ void reduce_tile(int j, float* __restrict__ y, int tid)
{
    const int b0 = (tid & 15) * 4;
    float4 c4[NEXP];
#pragma unroll
    for (int e = 0; e < NEXP; e++)
        c4[e] = *(const float4*)(g_c + e * BATCH + b0);

#pragma unroll
    for (int pass = 0; pass < 8; pass++) {
        const int o = j * 128 + pass * 16 + (tid >> 4);
        const float* p = g_part + (size_t)o * BATCH + b0;
        float ax = 0.f, ay = 0.f, az = 0.f, aw = 0.f;
#pragma unroll
        for (int kz = 0; kz < SPLITS; kz++) {
            float4 v = *(const float4*)(p + (size_t)kz * (OUTF * BATCH));
            float4 c = c4[kz >> 1];
            ax += c.x * v.x; ay += c.y * v.y; az += c.z * v.z; aw += c.w * v.w;
        }
        y[(size_t)(b0 + 0) * OUTF + o] = ax;
        y[(size_t)(b0 + 1) * OUTF + o] = ay;
        y[(size_t)(b0 + 2) * OUTF + o] = az;
        y[(size_t)(b0 + 3) * OUTF + o] = aw;
    }
}

// ---------------------------------------------------------------------------
// Fused single-launch kernel.
//   blockIdx.x < 8 : HMMA gemm CTA (o-tile bx, split kz=by). R8-proven shape:
//     M=128 (o), N=64 (b), K=512 in 8 chunks of 64, double-buffered 24KB
//     stages, 128B rows + 16B XOR swizzle, warp tile m32xn32, fp16/fp32 HMMA.
//     Stores RAW partials, then fence+counter arrive; 17th arriver reduces.
//   blockIdx.x == 8, by == 0 : gate CTA (runs concurrently under the gemm),
//     writes g_c, fences, arrives on all 8 counters.
//   blockIdx.x == 8, by > 0  : exit.
// ---------------------------------------------------------------------------
#define KC       64
#define NCH      8
#define A_BYTES  16384
#define STG      24576

__global__ void __launch_bounds__(256) fused_kernel(
    const float* __restrict__ x,
    const float* __restrict__ w,
    const float* __restrict__ align_conv,
    const float* __restrict__ W_ih,
    const float* __restrict__ b_ih,
    const float* __restrict__ b_hh,
    const float* __restrict__ W_att,
    const float* __restrict__ b_att,
    float* __restrict__ y)
{
    __shared__ __align__(16) uint8_t sm[2 * STG];
    __shared__ float red[8];
    __shared__ int s_flags;

    const int tid = threadIdx.x;

    // ======================= GATE CTA =======================
    if (blockIdx.x == 8) {
        if (blockIdx.y != 0) return;

        // gate: 4 batch samples per warp-octet; tid: b = tid>>2? keep proven
        // layout: 256 threads = 64 b x 4 slices of 256 floats each.
        {
            const int b = tid >> 2;          // batch sample
            const int q = tid & 3;           // quarter of the feature dim
            const float4* x4 = (const float4*)(x + (size_t)b * INF + q * 256);
            float s = 0.f;
#pragma unroll
            for (int i = 0; i < 64; i++) {
                float4 v = x4[i];
                s += (v.x + v.y) + (v.z + v.w);
            }
            // reduce 4 lanes (same warp, adjacent lanes)
            s += __shfl_xor_sync(0xffffffffu, s, 1);
            s += __shfl_xor_sync(0xffffffffu, s, 2);
            if (q == 0) {
                const float pooled = s * (1.0f / INF);
                float lg[NEXP];
                float mx = -1e30f;
#pragma unroll
                for (int e = 0; e < NEXP; e++) {
                    float v = b_att[e];
#pragma unroll
                    for (int j = 0; j < HID; j++) {
                        float rj = fmaxf(tanh_fast(pooled * W_ih[j] + b_ih[j] + b_hh[j]), 0.f);
                        v += rj * W_att[e * HID + j];
                    }
                    lg[e] = v;
                    mx = fmaxf(mx, v);
                }
                float sum = 0.f;
#pragma unroll
                for (int e = 0; e < NEXP; e++) { lg[e] = __expf(lg[e] - mx); sum += lg[e]; }
                const float inv = 1.f / sum;
#pragma unroll
                for (int e2 = 0; e2 < NEXP; e2++) {
                    float c = 0.f;
#pragma unroll
                    for (int f = 0; f < NEXP; f++)
                        c += (lg[f] * inv) * align_conv[f * NEXP + e2];
                    g_c[e2 * BATCH + b] = c;
                }
            }
        }
        __threadfence();
        __syncthreads();
        if (tid == 0) {
            int m = 0;
#pragma unroll
            for (int j = 0; j < 8; j++)
                if (atomicAdd(&g_cnt[j], 1) == 16) m |= (1 << j);
            s_flags = m;
        }
        __syncthreads();
        int flags = s_flags;
        if (flags) {
            __threadfence();
            for (int j = 0; j < 8; j++)
                if (flags & (1 << j)) {
                    reduce_tile(j, y, tid);
                    if (tid == 0) { __threadfence(); g_cnt[j] = 0; }
                }
        }
        return;
    }

    // ======================= GEMM CTA =======================
    const int wid = tid >> 5;
    const int lid = tid & 31;
    const int o0  = blockIdx.x * 128;
    const int kz  = blockIdx.y;
    const int e   = kz >> 1;
    const int i0  = (kz & 1) * 512;

    const float* wbase = w + ((size_t)e << 20) + (size_t)o0 * INF + i0;
    const float* xbase = x + i0;

    const int m0 = (wid & 3) * 32;     // warp M offset
    const int n0 = (wid >> 2) * 32;    // warp N offset

    float d[2][4][4];
#pragma unroll
    for (int i = 0; i < 2; i++)
#pragma unroll
        for (int j = 0; j < 4; j++)
#pragma unroll
            for (int k = 0; k < 4; k++) d[i][j][k] = 0.f;

    float4 av[8], bv[4];
    const uint32_t smb = smem_u32(sm);

    // ---- prologue: load stage 0 ----
    {
        const float4* ws = (const float4*)wbase;
        const float4* xs = (const float4*)xbase;
#pragma unroll
        for (int r = 0; r < 8; r++) {
            int g = tid + (r << 8);
            av[r] = ws[(g >> 4) * 256 + (g & 15)];
        }
#pragma unroll
        for (int r = 0; r < 4; r++) {
            int g = tid + (r << 8);
            bv[r] = xs[(g >> 4) * 256 + (g & 15)];
        }
    }

#define STORE_STAGE(sidx) do {                                                 \
    uint8_t* stg = sm + (sidx) * STG;                                          \
    _Pragma("unroll")                                                          \
    for (int r = 0; r < 8; r++) {                                              \
        int g = tid + (r << 8);                                                \
        uint32_t off = (uint32_t)((g >> 4) * 128 + (g & 15) * 8);              \
        off ^= (off >> 3) & 0x70u;                                             \
        uint2 pv; pv.x = h2bits(av[r].x, av[r].y);                             \
        pv.y = h2bits(av[r].z, av[r].w);                                       \
        *(uint2*)(stg + off) = pv;                                             \
    }                                                                          \
    _Pragma("unroll")                                                          \
    for (int r = 0; r < 4; r++) {                                              \
        int g = tid + (r << 8);                                                \
        uint32_t off = (uint32_t)((g >> 4) * 128 + (g & 15) * 8);              \
        off ^= (off >> 3) & 0x70u;                                             \
        uint2 pv; pv.x = h2bits(bv[r].x, bv[r].y);                             \
        pv.y = h2bits(bv[r].z, bv[r].w);                                       \
        *(uint2*)(stg + A_BYTES + off) = pv;                                   \
    }                                                                          \
} while (0)

    STORE_STAGE(0);
    __syncthreads();

    for (int kc = 0; kc < NCH; kc++) {
        const int cur = kc & 1;

        if (kc + 1 < NCH) {
            const float4* ws = (const float4*)(wbase + (kc + 1) * KC);
            const float4* xs = (const float4*)(xbase + (kc + 1) * KC);
#pragma unroll
            for (int r = 0; r < 8; r++) {
                int g = tid + (r << 8);
                av[r] = ws[(g >> 4) * 256 + (g & 15)];
            }
#pragma unroll
            for (int r = 0; r < 4; r++) {
                int g = tid + (r << 8);
                bv[r] = xs[(g >> 4) * 256 + (g & 15)];
            }
        }

        // ---- compute on stage `cur` ----
        const uint32_t sb = smb + cur * STG;
#pragma unroll
        for (int ks = 0; ks < 4; ks++) {
            uint32_t afr[2][4], bfr[2][4];
#pragma unroll
            for (int mf = 0; mf < 2; mf++) {
                uint32_t row = (uint32_t)(m0 + mf * 16 + (lid & 15));
                uint32_t kg  = (uint32_t)(ks * 2 + (lid >> 4));
                uint32_t off = row * 128 + kg * 16;
                off ^= (off >> 3) & 0x70u;
                ldsm4(afr[mf], sb + off);
            }
#pragma unroll
            for (int nh = 0; nh < 2; nh++) {
                uint32_t nrow = (uint32_t)(n0 + nh * 16 + (lid & 7) + ((lid >> 4) << 3));
                uint32_t kg   = (uint32_t)(ks * 2 + ((lid >> 3) & 1));
                uint32_t off  = nrow * 128 + kg * 16;
                off ^= (off >> 3) & 0x70u;
                ldsm4(bfr[nh], sb + A_BYTES + off);
            }
#pragma unroll
            for (int mf = 0; mf < 2; mf++) {
                mma16816(d[mf][0], afr[mf], bfr[0][0], bfr[0][1]);
                mma16816(d[mf][1], afr[mf], bfr[0][2], bfr[0][3]);
                mma16816(d[mf][2], afr[mf], bfr[1][0], bfr[1][1]);
                mma16816(d[mf][3], afr[mf], bfr[1][2], bfr[1][3]);
            }
        }

        __syncthreads();
        if (kc + 1 < NCH) {
            STORE_STAGE(cur ^ 1);
            __syncthreads();
        }
    }

    // ---- epilogue: STG.64 raw partials to g_part[kz][o][b] ----
    {
        float* part = g_part + (size_t)kz * (OUTF * BATCH);
        const int tg = lid >> 2;
        const int tc = (lid & 3) * 2;
#pragma unroll
        for (int mf = 0; mf < 2; mf++) {
#pragma unroll
            for (int nf = 0; nf < 4; nf++) {
                const int ol = m0 + mf * 16 + tg;
                const int bb = n0 + nf * 8 + tc;
                float2 v0; v0.x = d[mf][nf][0]; v0.y = d[mf][nf][1];
                float2 v1; v1.x = d[mf][nf][2]; v1.y = d[mf][nf][3];
                *(float2*)(part + (size_t)(o0 + ol) * BATCH + bb) = v0;
                *(float2*)(part + (size_t)(o0 + ol + 8) * BATCH + bb) = v1;
            }
        }
    }

    // ---- arrive; 17th arriver reduces this o-tile ----
    __threadfence();
    __syncthreads();
    if (tid == 0)
        s_flags = (atomicAdd(&g_cnt[blockIdx.x], 1) == 16);
    __syncthreads();
    if (s_flags) {
        __threadfence();
        reduce_tile(blockIdx.x, y, tid);
        if (tid == 0) { __threadfence(); g_cnt[blockIdx.x] = 0; }
    }
}

// ---------------------------------------------------------------------------
extern "C" void kernel_launch(void* const* d_in, const int* in_sizes, int n_in,
                              void* d_out, int out_size)
{
    (void)in_sizes; (void)n_in; (void)out_size;
    const float* x          = (const float*)d_in[0];
    const float* weight     = (const float*)d_in[1];
    const float* align_conv = (const float*)d_in[2];
    const float* W_ih       = (const float*)d_in[3];
    // d_in[4] = W_hh : unused (h0 == 0)
    const float* b_ih       = (const float*)d_in[5];
    const float* b_hh       = (const float*)d_in[6];
    const float* W_att      = (const float*)d_in[7];
    const float* b_att      = (const float*)d_in[8];
    float* y = (float*)d_out;

    fused_kernel<<<dim3(9, SPLITS), 256>>>(x, weight, align_conv, W_ih,
                                           b_ih, b_hh, W_att, b_att, y);
}

// round 17
// speedup vs baseline: 4.3514x; 4.3514x over previous
#include <cuda_runtime.h>
#include <cuda_fp16.h>
#include <cstdint>
#include <cstddef>

#define BATCH 64
#define INF   1024
#define OUTF  1024
#define NEXP  8
#define HID   8
#define SPLITS 16

// c[e][b] = sum_f att[b,f] * align_conv[f,e]  (produced inside the gemm)
__device__ float g_c[NEXP * BATCH];
// split-K RAW partials [kz][o][b] (4 MB static scratch); c applied in reduce
__device__ float g_part[SPLITS * OUTF * BATCH];
// x row-sum partials from the two e=0 gemm CTAs (kz=0: i<512, kz=1: i>=512)
__device__ float g_pool_part[2][BATCH];
// 2-arrival counter; second arriver runs the gate math, then resets to 0
__device__ int g_pcnt;

// ---------------------------------------------------------------------------
// arch-agnostic tensor-core helpers (sm_80+ PTX: valid at target sm_103)
// ---------------------------------------------------------------------------
__device__ __forceinline__ uint32_t smem_u32(const void* p) {
    uint32_t a;
    asm("{ .reg .u64 t; cvta.to.shared.u64 t, %1; cvt.u32.u64 %0, t; }"
        : "=r"(a) : "l"(p));
    return a;
}

__device__ __forceinline__ void ldsm4(uint32_t* r, uint32_t addr) {
    asm volatile("ldmatrix.sync.aligned.m8n8.x4.shared.b16 {%0,%1,%2,%3}, [%4];"
                 : "=r"(r[0]), "=r"(r[1]), "=r"(r[2]), "=r"(r[3]) : "r"(addr));
}

__device__ __forceinline__ void mma16816(float* d, const uint32_t* a,
                                         uint32_t b0, uint32_t b1) {
    asm volatile(
        "mma.sync.aligned.m16n8k16.row.col.f32.f16.f16.f32 "
        "{%0,%1,%2,%3}, {%4,%5,%6,%7}, {%8,%9}, {%0,%1,%2,%3};"
        : "+f"(d[0]), "+f"(d[1]), "+f"(d[2]), "+f"(d[3])
        : "r"(a[0]), "r"(a[1]), "r"(a[2]), "r"(a[3]), "r"(b0), "r"(b1));
}

__device__ __forceinline__ uint32_t h2bits(float a, float b) {
    __half2 h = __floats2half2_rn(a, b);   // low = a, high = b (k-order)
    return *reinterpret_cast<uint32_t*>(&h);
}

__device__ __forceinline__ float tanh_fast(float v) {
    float r;
    asm("tanh.approx.f32 %0, %1;" : "=f"(r) : "f"(v));
    return r;
}

// ---------------------------------------------------------------------------
// HMMA GEMM (R8-proven shape) + embedded pooling/gate:
//   part[kz][o][b] = sum_i w[e,o,i] * x[b,i]   (RAW; c applied in reduce)
//   CTA: M=128 (o), N=64 (b); grid = (8 o-tiles, 16 = 8 experts x 2 i-halves)
//   = 128 CTAs, single wave. K=512/CTA in 8 chunks of 64; double-buffered
//   24KB stages; 128B rows + 16B XOR swizzle; warp tile m32xn32.
//   The bx==0, kz<2 CTAs (e=0, both i-halves) cover x exactly once via the
//   B-loader: they accumulate x row-sums in registers (free), shfl-reduce,
//   and the 2nd arriver's warp 0 computes the full gate -> g_c.
// ---------------------------------------------------------------------------
#define KC       64
#define NCH      8
#define A_BYTES  16384
#define STG      24576

__global__ void __launch_bounds__(256) gemm_hmma(
    const float* __restrict__ x,
    const float* __restrict__ w,
    const float* __restrict__ align_conv,
    const float* __restrict__ W_ih,
    const float* __restrict__ b_ih,
    const float* __restrict__ b_hh,
    const float* __restrict__ W_att,
    const float* __restrict__ b_att)
{
    __shared__ __align__(16) uint8_t sm[2 * STG];
    __shared__ int s_last;
    const int tid = threadIdx.x;
    const int wid = tid >> 5;
    const int lid = tid & 31;
    const int o0  = blockIdx.x * 128;
    const int kz  = blockIdx.y;
    const int e   = kz >> 1;
    const int i0  = (kz & 1) * 512;

    const float* wbase = w + ((size_t)e << 20) + (size_t)o0 * INF + i0;
    const float* xbase = x + i0;

    const int m0 = (wid & 3) * 32;     // warp M offset
    const int n0 = (wid >> 2) * 32;    // warp N offset

    float d[2][4][4];
#pragma unroll
    for (int i = 0; i < 2; i++)
#pragma unroll
        for (int j = 0; j < 4; j++)
#pragma unroll
            for (int k = 0; k < 4; k++) d[i][j][k] = 0.f;

    float4 av[8], bv[4];
    float pacc[4] = {0.f, 0.f, 0.f, 0.f};   // x row-sum accumulators (pooling)
    const uint32_t smb = smem_u32(sm);

    // ---- prologue: load stage 0 ----
    {
        const float4* ws = (const float4*)wbase;
        const float4* xs = (const float4*)xbase;
#pragma unroll
        for (int r = 0; r < 8; r++) {
            int g = tid + (r << 8);
            av[r] = ws[(g >> 4) * 256 + (g & 15)];
        }
#pragma unroll
        for (int r = 0; r < 4; r++) {
            int g = tid + (r << 8);
            bv[r] = xs[(g >> 4) * 256 + (g & 15)];
            pacc[r] += (bv[r].x + bv[r].y) + (bv[r].z + bv[r].w);
        }
    }

#define STORE_STAGE(sidx) do {                                                 \
    uint8_t* stg = sm + (sidx) * STG;                                          \
    _Pragma("unroll")                                                          \
    for (int r = 0; r < 8; r++) {                                              \
        int g = tid + (r << 8);                                                \
        uint32_t off = (uint32_t)((g >> 4) * 128 + (g & 15) * 8);              \
        off ^= (off >> 3) & 0x70u;                                             \
        uint2 pv; pv.x = h2bits(av[r].x, av[r].y);                             \
        pv.y = h2bits(av[r].z, av[r].w);                                       \
        *(uint2*)(stg + off) = pv;                                             \
    }                                                                          \
    _Pragma("unroll")                                                          \
    for (int r = 0; r < 4; r++) {                                              \
        int g = tid + (r << 8);                                                \
        uint32_t off = (uint32_t)((g >> 4) * 128 + (g & 15) * 8);              \
        off ^= (off >> 3) & 0x70u;                                             \
        uint2 pv; pv.x = h2bits(bv[r].x, bv[r].y);                             \
        pv.y = h2bits(bv[r].z, bv[r].w);                                       \
        *(uint2*)(stg + A_BYTES + off) = pv;                                   \
    }                                                                          \
} while (0)

    STORE_STAGE(0);
    __syncthreads();

    for (int kc = 0; kc < NCH; kc++) {
        const int cur = kc & 1;

        if (kc + 1 < NCH) {
            const float4* ws = (const float4*)(wbase + (kc + 1) * KC);
            const float4* xs = (const float4*)(xbase + (kc + 1) * KC);
#pragma unroll
            for (int r = 0; r < 8; r++) {
                int g = tid + (r << 8);
                av[r] = ws[(g >> 4) * 256 + (g & 15)];
            }
#pragma unroll
            for (int r = 0; r < 4; r++) {
                int g = tid + (r << 8);
                bv[r] = xs[(g >> 4) * 256 + (g & 15)];
                pacc[r] += (bv[r].x + bv[r].y) + (bv[r].z + bv[r].w);
            }
        }

        // ---- compute on stage `cur` ----
        const uint32_t sb = smb + cur * STG;
#pragma unroll
        for (int ks = 0; ks < 4; ks++) {
            uint32_t afr[2][4], bfr[2][4];
#pragma unroll
            for (int mf = 0; mf < 2; mf++) {
                uint32_t row = (uint32_t)(m0 + mf * 16 + (lid & 15));
                uint32_t kg  = (uint32_t)(ks * 2 + (lid >> 4));
                uint32_t off = row * 128 + kg * 16;
                off ^= (off >> 3) & 0x70u;
                ldsm4(afr[mf], sb + off);
            }
#pragma unroll
            for (int nh = 0; nh < 2; nh++) {
                uint32_t nrow = (uint32_t)(n0 + nh * 16 + (lid & 7) + ((lid >> 4) << 3));
                uint32_t kg   = (uint32_t)(ks * 2 + ((lid >> 3) & 1));
                uint32_t off  = nrow * 128 + kg * 16;
                off ^= (off >> 3) & 0x70u;
                ldsm4(bfr[nh], sb + A_BYTES + off);
            }
#pragma unroll
            for (int mf = 0; mf < 2; mf++) {
                mma16816(d[mf][0], afr[mf], bfr[0][0], bfr[0][1]);
                mma16816(d[mf][1], afr[mf], bfr[0][2], bfr[0][3]);
                mma16816(d[mf][2], afr[mf], bfr[1][0], bfr[1][1]);
                mma16816(d[mf][3], afr[mf], bfr[1][2], bfr[1][3]);
            }
        }

        __syncthreads();
        if (kc + 1 < NCH) {
            STORE_STAGE(cur ^ 1);
            __syncthreads();
        }
    }

    // ---- epilogue: STG.64 raw partials to g_part[kz][o][b] ----
    {
        float* part = g_part + (size_t)kz * (OUTF * BATCH);
        const int tg = lid >> 2;
        const int tc = (lid & 3) * 2;
#pragma unroll
        for (int mf = 0; mf < 2; mf++) {
#pragma unroll
            for (int nf = 0; nf < 4; nf++) {
                const int ol = m0 + mf * 16 + tg;
                const int bb = n0 + nf * 8 + tc;
                float2 v0; v0.x = d[mf][nf][0]; v0.y = d[mf][nf][1];
                float2 v1; v1.x = d[mf][nf][2]; v1.y = d[mf][nf][3];
                *(float2*)(part + (size_t)(o0 + ol) * BATCH + bb) = v0;
                *(float2*)(part + (size_t)(o0 + ol + 8) * BATCH + bb) = v1;
            }
        }
    }

    // ---- pooling + gate tail (only the two e=0 CTAs of o-tile 0) ----
    if (blockIdx.x == 0 && kz < 2) {
        // 16 threads share each x row (consecutive, 16-aligned): shfl-reduce
        // in fixed order -> deterministic row sums.
#pragma unroll
        for (int r = 0; r < 4; r++) {
            float s = pacc[r];
            s += __shfl_xor_sync(0xffffffffu, s, 1);
            s += __shfl_xor_sync(0xffffffffu, s, 2);
            s += __shfl_xor_sync(0xffffffffu, s, 4);
            s += __shfl_xor_sync(0xffffffffu, s, 8);
            if ((tid & 15) == 0)
                g_pool_part[kz][(tid + (r << 8)) >> 4] = s;
        }
        __threadfence();
        __syncthreads();
        if (tid == 0) s_last = (atomicAdd(&g_pcnt, 1) == 1);
        __syncthreads();
        if (s_last) {
            __threadfence();
            if (tid < 32) {
#pragma unroll
                for (int h = 0; h < 2; h++) {
                    const int b = tid + h * 32;
                    const float pooled =
                        (g_pool_part[0][b] + g_pool_part[1][b]) * (1.0f / INF);
                    float rj[HID];
#pragma unroll
                    for (int j = 0; j < HID; j++)
                        rj[j] = fmaxf(tanh_fast(pooled * W_ih[j] + b_ih[j] + b_hh[j]), 0.f);
                    float lg[NEXP];
                    float mx = -1e30f;
#pragma unroll
                    for (int e2 = 0; e2 < NEXP; e2++) {
                        float v = b_att[e2];
#pragma unroll
                        for (int j = 0; j < HID; j++) v += rj[j] * W_att[e2 * HID + j];
                        lg[e2] = v;
                        mx = fmaxf(mx, v);
                    }
                    float sum = 0.f;
#pragma unroll
                    for (int e2 = 0; e2 < NEXP; e2++) { lg[e2] = __expf(lg[e2] - mx); sum += lg[e2]; }
                    const float inv = 1.f / sum;
#pragma unroll
                    for (int e2 = 0; e2 < NEXP; e2++) {
                        float c = 0.f;
#pragma unroll
                        for (int f = 0; f < NEXP; f++)
                            c += (lg[f] * inv) * align_conv[f * NEXP + e2];
                        g_c[e2 * BATCH + b] = c;
                    }
                }
            }
            __syncthreads();
            if (tid == 0) g_pcnt = 0;   // reset for next graph replay
        }
    }
}

// ---------------------------------------------------------------------------
// Split-K reduce + gate apply + transpose:
//   y[b][o] = sum_kz c[b, e(kz)] * part[kz][o][b],  e(kz) = kz>>1.
// Kernel boundary orders g_c/g_part before this launch. 4 MB is L2-resident.
// ---------------------------------------------------------------------------
__global__ void __launch_bounds__(256) reduce_kernel(float* __restrict__ y)
{
    const int gid = blockIdx.x * 256 + threadIdx.x;   // 0..65535
    const int o = gid >> 6;
    const int b = gid & 63;
    const float* p = g_part + (size_t)o * BATCH + b;

    float cv[NEXP];
#pragma unroll
    for (int e = 0; e < NEXP; e++) cv[e] = g_c[e * BATCH + b];

    float a0 = 0.f, a1 = 0.f, a2 = 0.f, a3 = 0.f;
#pragma unroll
    for (int kzi = 0; kzi < SPLITS; kzi += 4) {
        a0 += cv[(kzi + 0) >> 1] * p[(size_t)(kzi + 0) * (OUTF * BATCH)];
        a1 += cv[(kzi + 1) >> 1] * p[(size_t)(kzi + 1) * (OUTF * BATCH)];
        a2 += cv[(kzi + 2) >> 1] * p[(size_t)(kzi + 2) * (OUTF * BATCH)];
        a3 += cv[(kzi + 3) >> 1] * p[(size_t)(kzi + 3) * (OUTF * BATCH)];
    }
    y[(size_t)b * OUTF + o] = (a0 + a1) + (a2 + a3);
}

// ---------------------------------------------------------------------------
extern "C" void kernel_launch(void* const* d_in, const int* in_sizes, int n_in,
                              void* d_out, int out_size)
{
    (void)in_sizes; (void)n_in; (void)out_size;
    const float* x          = (const float*)d_in[0];
    const float* weight     = (const float*)d_in[1];
    const float* align_conv = (const float*)d_in[2];
    const float* W_ih       = (const float*)d_in[3];
    // d_in[4] = W_hh : unused (h0 == 0)
    const float* b_ih       = (const float*)d_in[5];
    const float* b_hh       = (const float*)d_in[6];
    const float* W_att      = (const float*)d_in[7];
    const float* b_att      = (const float*)d_in[8];
    float* y = (float*)d_out;

    gemm_hmma<<<dim3(OUTF / 128, SPLITS), 256>>>(x, weight, align_conv,
                                                 W_ih, b_ih, b_hh, W_att, b_att);
    reduce_kernel<<<(OUTF * BATCH) / 256, 256>>>(y);
}